// round 7
// baseline (speedup 1.0000x reference)
#include <cuda_runtime.h>
#include <cstdint>
#include <math.h>

// ---------------- problem constants ----------------
#define T_SEQ 1000
#define BATCH 16
#define M_ROWS (BATCH * T_SEQ)   // 16000
#define NBLK  64                 // blocks per LSTM direction

// ---------------- scratch (device globals; no cudaMalloc allowed) ----------
__device__ float g_h1 [M_ROWS * 1024];
__device__ float g_h2 [(size_t)M_ROWS * 2560];
__device__ float g_xgf[M_ROWS * 1024];
__device__ float g_xgb[M_ROWS * 1024];
__device__ float g_out0[M_ROWS * 512];
__device__ float g_out1[M_ROWS * 512];
__device__ float g_hseq[2 * (T_SEQ + 1) * 4096];  // [dir][step][16*256], step 0 = zeros
__device__ unsigned g_flags[2 * NBLK];            // [dir][blk] completed-step counters

// ================= PTX helpers =================
__device__ __forceinline__ uint32_t smem_u32(const void* p) {
    uint32_t a;
    asm("{ .reg .u64 t; cvta.to.shared.u64 t, %1; cvt.u32.u64 %0, t; }" : "=r"(a) : "l"(p));
    return a;
}
__device__ __forceinline__ void cpa16(uint32_t dst, const void* src) {
    asm volatile("cp.async.cg.shared.global [%0], [%1], 16;" :: "r"(dst), "l"(src) : "memory");
}
__device__ __forceinline__ void sts_zero16(uint32_t dst) {
    asm volatile("st.shared.v4.b32 [%0], {%1,%1,%1,%1};" :: "r"(dst), "r"(0u) : "memory");
}
#define CP_COMMIT() asm volatile("cp.async.commit_group;" ::: "memory")
#define CP_WAIT1()  asm volatile("cp.async.wait_group 1;" ::: "memory")
#define CP_WAIT0()  asm volatile("cp.async.wait_group 0;" ::: "memory")

__device__ __forceinline__ void ldsm4(uint32_t addr, uint32_t& r0, uint32_t& r1,
                                      uint32_t& r2, uint32_t& r3) {
    asm volatile("ldmatrix.sync.aligned.m8n8.x4.shared.b16 {%0,%1,%2,%3}, [%4];"
                 : "=r"(r0), "=r"(r1), "=r"(r2), "=r"(r3) : "r"(addr));
}
__device__ __forceinline__ void mma_tf32(float* d, const uint32_t* a, const uint32_t* b) {
    asm volatile(
        "mma.sync.aligned.m16n8k8.row.col.f32.tf32.tf32.f32 "
        "{%0,%1,%2,%3}, {%4,%5,%6,%7}, {%8,%9}, {%0,%1,%2,%3};"
        : "+f"(d[0]), "+f"(d[1]), "+f"(d[2]), "+f"(d[3])
        : "r"(a[0]), "r"(a[1]), "r"(a[2]), "r"(a[3]), "r"(b[0]), "r"(b[1]));
}
// split fp32 (bit pattern in v) into tf32 hi + tf32 lo, hi+lo ~= v to ~2^-22
__device__ __forceinline__ void tf32_split(uint32_t v, uint32_t& hi, uint32_t& lo) {
    float f = __uint_as_float(v);
    asm("cvt.rna.tf32.f32 %0, %1;" : "=r"(hi) : "f"(f));
    float r = f - __uint_as_float(hi);
    asm("cvt.rna.tf32.f32 %0, %1;" : "=r"(lo) : "f"(r));
}
// relaxed flag store (release is provided by the preceding __threadfence)
__device__ __forceinline__ void st_flag_cg(unsigned* p, unsigned v) {
    asm volatile("st.global.cg.u32 [%0], %1;" :: "l"(p), "r"(v) : "memory");
}

// ================= tensor-core 3xTF32 GEMM (mma.sync path) =================
// C[M,N] = A[M,K] @ Bw[N,K]^T + bias1 (+bias2), optional ReLU.
// 128x128 CTA tile, 8 warps in 2(m)x4(n), warp tile 64x32.
// K-chunk 32, 2-stage cp.async double buffer, 2 CTAs/SM.
#define ROWB   144
#define TILEB  (128 * ROWB)          // 18432 per operand
#define STAGEB (2 * TILEB)           // 36864 per stage (A + B)
#define GEMM_SMEM_BYTES (1024 + 2 * STAGEB)

__global__ __launch_bounds__(256, 2)
void tc_gemm(const float* __restrict__ A, const float* __restrict__ Bw,
             const float* __restrict__ bias1, const float* __restrict__ bias2,
             float* __restrict__ C, int M, int N, int K, int relu)
{
    extern __shared__ __align__(1024) char smem[];
    const int tid = threadIdx.x;
    const int wid = tid >> 5;
    const int lid = tid & 31;
    const int wm  = wid & 1;          // 0..1 (m)
    const int wn  = wid >> 1;         // 0..3 (n)
    const uint32_t sbase = smem_u32(smem);
    float* bsm = (float*)(smem);      // 128 floats bias
    const uint32_t tiles = sbase + 1024;

    const int rowBase = blockIdx.y * 128;
    const int colBase = blockIdx.x * 128;

    if (tid < 128) bsm[tid] = bias1[colBase + tid] + (bias2 ? bias2[colBase + tid] : 0.f);

    float acc[4][4][4];
    #pragma unroll
    for (int i = 0; i < 4; i++)
        #pragma unroll
        for (int j = 0; j < 4; j++)
            #pragma unroll
            for (int q = 0; q < 4; q++) acc[i][j][q] = 0.f;

    const int NC = (K + 31) / 32;

    // chunk loader: A 1024 granules + B 1024 granules (16B each), 8/thread
    auto load_chunk = [&](int stage, int k0) {
        uint32_t abase = tiles + stage * STAGEB;
        uint32_t bbase = abase + TILEB;
        #pragma unroll
        for (int i = 0; i < 8; i++) {
            int id  = tid + (i << 8);
            int row = (id >> 3) & 127;
            int g   = id & 7;
            int k   = k0 + (g << 2);
            if (id < 1024) {
                uint32_t dst = abase + row * ROWB + (g << 4);
                if (k < K) cpa16(dst, A + (size_t)(rowBase + row) * K + k);
                else       sts_zero16(dst);
            } else {
                uint32_t dst = bbase + row * ROWB + (g << 4);
                if (k < K) cpa16(dst, Bw + (size_t)(colBase + row) * K + k);
                else       sts_zero16(dst);
            }
        }
    };

    load_chunk(0, 0);
    CP_COMMIT();

    for (int c = 0; c < NC; c++) {
        if (c + 1 < NC) { load_chunk((c + 1) & 1, (c + 1) * 32); CP_COMMIT(); CP_WAIT1(); }
        else            { CP_WAIT0(); }
        __syncthreads();

        uint32_t abase = tiles + (c & 1) * STAGEB;
        uint32_t bbase = abase + TILEB;
        const int lm = lid >> 3;            // which sub-matrix this thread addresses
        const int lr = lid & 7;

        #pragma unroll
        for (int ks = 0; ks < 4; ks++) {
            uint32_t ah[4][4], al[4][4], bh[4][2], bl[4][2];
            // A fragments: 4 m16 tiles
            #pragma unroll
            for (int mt = 0; mt < 4; mt++) {
                uint32_t raw[4];
                uint32_t r = wm * 64 + mt * 16 + ((lm & 1) << 3) + lr;
                uint32_t addr = abase + r * ROWB + (ks << 5) + ((lm >> 1) << 4);
                ldsm4(addr, raw[0], raw[1], raw[2], raw[3]);
                #pragma unroll
                for (int q = 0; q < 4; q++) tf32_split(raw[q], ah[mt][q], al[mt][q]);
            }
            // B fragments: 2 x4 loads cover 4 n8 tiles
            #pragma unroll
            for (int bt = 0; bt < 2; bt++) {
                uint32_t raw[4];
                uint32_t r = wn * 32 + bt * 16 + ((lm >> 1) << 3) + lr;
                uint32_t addr = bbase + r * ROWB + (ks << 5) + ((lm & 1) << 4);
                ldsm4(addr, raw[0], raw[1], raw[2], raw[3]);
                tf32_split(raw[0], bh[2 * bt][0],     bl[2 * bt][0]);
                tf32_split(raw[1], bh[2 * bt][1],     bl[2 * bt][1]);
                tf32_split(raw[2], bh[2 * bt + 1][0], bl[2 * bt + 1][0]);
                tf32_split(raw[3], bh[2 * bt + 1][1], bl[2 * bt + 1][1]);
            }
            #pragma unroll
            for (int mt = 0; mt < 4; mt++)
                #pragma unroll
                for (int nt = 0; nt < 4; nt++) {
                    mma_tf32(acc[mt][nt], al[mt], bh[nt]);
                    mma_tf32(acc[mt][nt], ah[mt], bl[nt]);
                    mma_tf32(acc[mt][nt], ah[mt], bh[nt]);
                }
        }
        __syncthreads();
    }

    // epilogue: c0:(g,2tg) c1:(g,2tg+1) c2:(g+8,2tg) c3:(g+8,2tg+1)
    const int g  = lid >> 2;
    const int tg = lid & 3;
    #pragma unroll
    for (int mt = 0; mt < 4; mt++) {
        int r0 = rowBase + wm * 64 + mt * 16 + g;
        #pragma unroll
        for (int nt = 0; nt < 4; nt++) {
            int cc = wn * 32 + nt * 8 + 2 * tg;
            float b0 = bsm[cc], b1 = bsm[cc + 1];
            float2 v0 = make_float2(acc[mt][nt][0] + b0, acc[mt][nt][1] + b1);
            float2 v1 = make_float2(acc[mt][nt][2] + b0, acc[mt][nt][3] + b1);
            if (relu) {
                v0.x = fmaxf(v0.x, 0.f); v0.y = fmaxf(v0.y, 0.f);
                v1.x = fmaxf(v1.x, 0.f); v1.y = fmaxf(v1.y, 0.f);
            }
            *(float2*)&C[(size_t)r0 * N + colBase + cc] = v0;
            *(float2*)&C[(size_t)(r0 + 8) * N + colBase + cc] = v1;
        }
    }
}

// ---------------- init: zero flags + step-0 h rows --------------------------
__global__ void init_rec_kernel()
{
    int t = blockIdx.x * blockDim.x + threadIdx.x;
    if (t < 2 * NBLK) g_flags[t] = 0u;
    // zero step-0 row of both directions (never written by the recurrence)
    if (t < 4096) {
        g_hseq[t] = 0.f;
        g_hseq[(size_t)(T_SEQ + 1) * 4096 + t] = 0.f;
    }
}

// ---------------- persistent bidirectional LSTM recurrence -----------------
// grid = 128 blocks: [0,64) forward, [64,128) backward. Each block owns 4
// hidden units (16 gate cols x 16 batches = 256 dot products of length 256).
// h history: write-once rows g_hseq[dir][step][.].
// Barrier: distributed relaxed flags (st.cg after threadfence), 64 parallel
// pollers with __ldcg + nanosleep backoff, reader-side threadfence.
__global__ __launch_bounds__(256) void lstm_rec_kernel(
    const float* __restrict__ xg_f, const float* __restrict__ xg_b,
    const float* __restrict__ whh_f, const float* __restrict__ whh_b,
    float* __restrict__ out)
{
    const int dir   = blockIdx.x / NBLK;
    const int blk   = blockIdx.x % NBLK;
    const int jbase = blk * 4;
    const int tid   = threadIdx.x;
    const int b     = tid >> 4;
    const int col   = tid & 15;
    const int gate  = col >> 2;
    const int jl    = col & 3;
    const int xgcol = gate * 256 + jbase + jl;

    const float* xg  = dir ? xg_b  : xg_f;
    const float* whh = dir ? whh_b : whh_f;

    __shared__ float wsm[16][260];
    __shared__ float hsm[16][260];
    __shared__ float gsm[16][16];

    for (int i = tid; i < 16 * 256; i += 256) {
        int c = i >> 8, k = i & 255;
        int g2 = c >> 2, j2 = c & 3;
        wsm[c][k] = whh[(g2 * 256 + jbase + j2) * 256 + k];
    }

    float cst = 0.f;
    const int ub = tid >> 2, uj = tid & 3;
    float* hseq = g_hseq + (size_t)dir * (T_SEQ + 1) * 4096;
    unsigned* flags = g_flags + dir * NBLK;
    __syncthreads();

    for (int iter = 0; iter < T_SEQ; iter++) {
        // load h_prev = hseq[iter] (fresh row, gated by previous barrier)
        {
            const float4* src = (const float4*)(hseq + (size_t)iter * 4096);
            #pragma unroll
            for (int i = 0; i < 4; i++) {
                int id = tid * 4 + i;
                float4 v = __ldcg(&src[id]);
                int bb = id >> 6;
                int kk = (id & 63) << 2;
                *(float4*)&hsm[bb][kk] = v;
            }
        }
        __syncthreads();

        const int t = dir ? (T_SEQ - 1 - iter) : iter;
        float xv = __ldg(&xg[(size_t)(b * T_SEQ + t) * 1024 + xgcol]);

        float acc = 0.f;
        const float4* wr = (const float4*)&wsm[col][0];
        const float4* hr = (const float4*)&hsm[b][0];
        #pragma unroll 8
        for (int k4 = 0; k4 < 64; k4++) {
            float4 w = wr[k4];
            float4 h = hr[k4];
            acc = fmaf(w.x, h.x, acc);
            acc = fmaf(w.y, h.y, acc);
            acc = fmaf(w.z, h.z, acc);
            acc = fmaf(w.w, h.w, acc);
        }
        gsm[b][col] = acc + xv;
        __syncthreads();

        if (tid < 64) {
            float gi = gsm[ub][0  + uj];
            float gf = gsm[ub][4  + uj];
            float gg = gsm[ub][8  + uj];
            float go = gsm[ub][12 + uj];
            float si = 1.f / (1.f + expf(-gi));
            float sf = 1.f / (1.f + expf(-gf));
            float tg = tanhf(gg);
            float so = 1.f / (1.f + expf(-go));
            cst = sf * cst + si * tg;
            float hv = so * tanhf(cst);
            hseq[(size_t)(iter + 1) * 4096 + ub * 256 + jbase + uj] = hv;
            out[(size_t)(ub * T_SEQ + t) * 512 + dir * 256 + jbase + uj] = hv;
            __threadfence();   // release: h row visible before flag store
        }
        __syncthreads();       // all writers fenced before publish

        if (tid == 0) st_flag_cg(&flags[blk], (unsigned)(iter + 1));
        // distributed arrival detection: thread t polls block t's flag (relaxed)
        if (tid < NBLK) {
            const unsigned target = (unsigned)(iter + 1);
            while (__ldcg(&flags[tid]) < target) { __nanosleep(20); }
        }
        __syncthreads();
        __threadfence();       // acquire: order h-row loads after flag observation
    }
}

// ---------------- final FC: [16000,512] @ [29,512]^T + b -------------------
__global__ __launch_bounds__(256) void fc_kernel(
    const float* __restrict__ A, const float* __restrict__ W,
    const float* __restrict__ bias, float* __restrict__ out)
{
    __shared__ float as[8][512];
    int r0 = blockIdx.x * 8;
    for (int i = threadIdx.x; i < 8 * 512; i += 256)
        as[i >> 9][i & 511] = A[(size_t)(r0 + (i >> 9)) * 512 + (i & 511)];
    __syncthreads();

    int r = threadIdx.x >> 5;
    int c = threadIdx.x & 31;
    if (c < 29) {
        const float* w = W + c * 512;
        float acc = 0.f;
        #pragma unroll 8
        for (int k = 0; k < 512; k++) acc = fmaf(as[r][k], __ldg(&w[k]), acc);
        out[(size_t)(r0 + r) * 29 + c] = acc + bias[c];
    }
}

// ---------------- launch ---------------------------------------------------
extern "C" void kernel_launch(void* const* d_in, const int* in_sizes, int n_in,
                              void* d_out, int out_size)
{
    (void)in_sizes; (void)n_in; (void)out_size;
    const float* x        = (const float*)d_in[0];
    const float* fe_w1    = (const float*)d_in[1];
    const float* fe_b1    = (const float*)d_in[2];
    const float* fe_w2    = (const float*)d_in[3];
    const float* fe_b2    = (const float*)d_in[4];
    const float* w_ih_l0f = (const float*)d_in[5];
    const float* w_hh_l0f = (const float*)d_in[6];
    const float* b_ih_l0f = (const float*)d_in[7];
    const float* b_hh_l0f = (const float*)d_in[8];
    const float* w_ih_l0b = (const float*)d_in[9];
    const float* w_hh_l0b = (const float*)d_in[10];
    const float* b_ih_l0b = (const float*)d_in[11];
    const float* b_hh_l0b = (const float*)d_in[12];
    const float* w_ih_l1f = (const float*)d_in[13];
    const float* w_hh_l1f = (const float*)d_in[14];
    const float* b_ih_l1f = (const float*)d_in[15];
    const float* b_hh_l1f = (const float*)d_in[16];
    const float* w_ih_l1b = (const float*)d_in[17];
    const float* w_hh_l1b = (const float*)d_in[18];
    const float* b_ih_l1b = (const float*)d_in[19];
    const float* b_hh_l1b = (const float*)d_in[20];
    const float* fc_w     = (const float*)d_in[21];
    const float* fc_b     = (const float*)d_in[22];
    float* out = (float*)d_out;

    float *h1, *h2, *xgf, *xgb, *o0, *o1;
    cudaGetSymbolAddress((void**)&h1,  g_h1);
    cudaGetSymbolAddress((void**)&h2,  g_h2);
    cudaGetSymbolAddress((void**)&xgf, g_xgf);
    cudaGetSymbolAddress((void**)&xgb, g_xgb);
    cudaGetSymbolAddress((void**)&o0,  g_out0);
    cudaGetSymbolAddress((void**)&o1,  g_out1);

    cudaFuncSetAttribute(tc_gemm, cudaFuncAttributeMaxDynamicSharedMemorySize, GEMM_SMEM_BYTES);

    // feature extractor
    tc_gemm<<<dim3(1024 / 128, M_ROWS / 128), 256, GEMM_SMEM_BYTES>>>(x,  fe_w1, fe_b1, nullptr, h1, M_ROWS, 1024, 80,   1);
    tc_gemm<<<dim3(2560 / 128, M_ROWS / 128), 256, GEMM_SMEM_BYTES>>>(h1, fe_w2, fe_b2, nullptr, h2, M_ROWS, 2560, 1024, 1);

    // layer 0: input-gate precompute + bidirectional recurrence
    tc_gemm<<<dim3(8, M_ROWS / 128), 256, GEMM_SMEM_BYTES>>>(h2, w_ih_l0f, b_ih_l0f, b_hh_l0f, xgf, M_ROWS, 1024, 2560, 0);
    tc_gemm<<<dim3(8, M_ROWS / 128), 256, GEMM_SMEM_BYTES>>>(h2, w_ih_l0b, b_ih_l0b, b_hh_l0b, xgb, M_ROWS, 1024, 2560, 0);
    init_rec_kernel<<<64, 256>>>();
    lstm_rec_kernel<<<2 * NBLK, 256>>>(xgf, xgb, w_hh_l0f, w_hh_l0b, o0);

    // layer 1
    tc_gemm<<<dim3(8, M_ROWS / 128), 256, GEMM_SMEM_BYTES>>>(o0, w_ih_l1f, b_ih_l1f, b_hh_l1f, xgf, M_ROWS, 1024, 512, 0);
    tc_gemm<<<dim3(8, M_ROWS / 128), 256, GEMM_SMEM_BYTES>>>(o0, w_ih_l1b, b_ih_l1b, b_hh_l1b, xgb, M_ROWS, 1024, 512, 0);
    init_rec_kernel<<<64, 256>>>();
    lstm_rec_kernel<<<2 * NBLK, 256>>>(xgf, xgb, w_hh_l1f, w_hh_l1b, o1);

    // classifier
    fc_kernel<<<M_ROWS / 8, 256>>>(o1, fc_w, fc_b, out);
}

// round 8
// speedup vs baseline: 2.6337x; 2.6337x over previous
#include <cuda_runtime.h>
#include <cuda_bf16.h>
#include <cstdint>
#include <math.h>

// ---------------- problem constants ----------------
#define T_SEQ 1000
#define BATCH 16
#define M_ROWS (BATCH * T_SEQ)   // 16000
#define NBLK  64                 // blocks per LSTM direction

// ---------------- fp32 scratch ----------------
__device__ float g_h1 [M_ROWS * 1024];
__device__ float g_h2 [(size_t)M_ROWS * 2560];
__device__ float g_xgf[M_ROWS * 1024];
__device__ float g_xgb[M_ROWS * 1024];
__device__ float g_out0[M_ROWS * 512];
__device__ float g_out1[M_ROWS * 512];
__device__ float g_hbuf[2 * 2 * 4096];   // [dir][parity][16*256]
__device__ unsigned g_barctr[2];

// ---------------- bf16 split scratch ----------------
__device__ __nv_bfloat16 g_xhi [M_ROWS * 80],    g_xlo [M_ROWS * 80];
__device__ __nv_bfloat16 g_w1hi[1024 * 80],      g_w1lo[1024 * 80];
__device__ __nv_bfloat16 g_w2hi[2560 * 1024],    g_w2lo[2560 * 1024];
__device__ __nv_bfloat16 g_h1hi[M_ROWS * 1024],  g_h1lo[M_ROWS * 1024];
__device__ __nv_bfloat16 g_h2hi[(size_t)M_ROWS * 2560], g_h2lo[(size_t)M_ROWS * 2560];
__device__ __nv_bfloat16 g_wl0fhi[1024 * 2560],  g_wl0flo[1024 * 2560];
__device__ __nv_bfloat16 g_wl0bhi[1024 * 2560],  g_wl0blo[1024 * 2560];
__device__ __nv_bfloat16 g_wl1fhi[1024 * 512],   g_wl1flo[1024 * 512];
__device__ __nv_bfloat16 g_wl1bhi[1024 * 512],   g_wl1blo[1024 * 512];
__device__ __nv_bfloat16 g_o0hi[M_ROWS * 512],   g_o0lo[M_ROWS * 512];

// ================= PTX helpers =================
__device__ __forceinline__ uint32_t smem_u32(const void* p) {
    uint32_t a;
    asm("{ .reg .u64 t; cvta.to.shared.u64 t, %1; cvt.u32.u64 %0, t; }" : "=r"(a) : "l"(p));
    return a;
}
__device__ __forceinline__ void cpa16(uint32_t dst, const void* src) {
    asm volatile("cp.async.cg.shared.global [%0], [%1], 16;" :: "r"(dst), "l"(src) : "memory");
}
__device__ __forceinline__ void sts_zero16(uint32_t dst) {
    asm volatile("st.shared.v4.b32 [%0], {%1,%1,%1,%1};" :: "r"(dst), "r"(0u) : "memory");
}
#define CP_COMMIT() asm volatile("cp.async.commit_group;" ::: "memory")
#define CP_WAIT1()  asm volatile("cp.async.wait_group 1;" ::: "memory")
#define CP_WAIT0()  asm volatile("cp.async.wait_group 0;" ::: "memory")

__device__ __forceinline__ void ldsm4(uint32_t addr, uint32_t& r0, uint32_t& r1,
                                      uint32_t& r2, uint32_t& r3) {
    asm volatile("ldmatrix.sync.aligned.m8n8.x4.shared.b16 {%0,%1,%2,%3}, [%4];"
                 : "=r"(r0), "=r"(r1), "=r"(r2), "=r"(r3) : "r"(addr));
}
__device__ __forceinline__ void mma_bf16(float* d, const uint32_t* a, const uint32_t* b) {
    asm volatile(
        "mma.sync.aligned.m16n8k16.row.col.f32.bf16.bf16.f32 "
        "{%0,%1,%2,%3}, {%4,%5,%6,%7}, {%8,%9}, {%0,%1,%2,%3};"
        : "+f"(d[0]), "+f"(d[1]), "+f"(d[2]), "+f"(d[3])
        : "r"(a[0]), "r"(a[1]), "r"(a[2]), "r"(a[3]), "r"(b[0]), "r"(b[1]));
}

// ---------------- fp32 -> bf16 hi/lo split kernel ----------------
__global__ void conv_split_kernel(const float* __restrict__ src,
                                  __nv_bfloat16* __restrict__ hi,
                                  __nv_bfloat16* __restrict__ lo, int n)
{
    int i = blockIdx.x * blockDim.x + threadIdx.x;
    if (i < n) {
        float v = src[i];
        __nv_bfloat16 h = __float2bfloat16_rn(v);
        hi[i] = h;
        lo[i] = __float2bfloat16_rn(v - __bfloat162float(h));
    }
}

// ================= tensor-core bf16x3 GEMM =================
// C = A @ Bw^T + bias1 (+bias2), opt ReLU.  A,Bw given as bf16 hi/lo pairs.
// acc += Ah*Bh + Ah*Bl + Al*Bh  (fp32 accumulate; ~1e-5 per-output error)
// 128x128 CTA tile, 8 warps 2(m)x4(n), warp tile 64x32; K-chunk 32 (2x k16),
// 2-stage cp.async double buffer. SMEM rows: 64B data + 16B pad = 80B stride
// (16B-aligned rows, ldmatrix bank-conflict-free).
#define ROWB   80
#define TILEB  (128 * ROWB)          // 10240 per operand part
#define STAGEB (4 * TILEB)           // Ahi,Alo,Bhi,Blo = 40960 per stage
#define GEMM_SMEM_BYTES (1024 + 2 * STAGEB)

__global__ __launch_bounds__(256, 2)
void tc_gemm(const __nv_bfloat16* __restrict__ Ahi, const __nv_bfloat16* __restrict__ Alo,
             const __nv_bfloat16* __restrict__ Bhi, const __nv_bfloat16* __restrict__ Blo,
             const float* __restrict__ bias1, const float* __restrict__ bias2,
             float* __restrict__ C,
             __nv_bfloat16* __restrict__ Chi, __nv_bfloat16* __restrict__ Clo,
             int M, int N, int K, int relu)
{
    extern __shared__ __align__(1024) char smem[];
    const int tid = threadIdx.x;
    const int wid = tid >> 5;
    const int lid = tid & 31;
    const int wm  = wid & 1;
    const int wn  = wid >> 1;
    const uint32_t sbase = smem_u32(smem);
    float* bsm = (float*)(smem);
    const uint32_t tiles = sbase + 1024;

    const int rowBase = blockIdx.y * 128;
    const int colBase = blockIdx.x * 128;

    if (tid < 128) bsm[tid] = bias1[colBase + tid] + (bias2 ? bias2[colBase + tid] : 0.f);

    float acc[4][4][4];
    #pragma unroll
    for (int i = 0; i < 4; i++)
        #pragma unroll
        for (int j = 0; j < 4; j++)
            #pragma unroll
            for (int q = 0; q < 4; q++) acc[i][j][q] = 0.f;

    const int NC = (K + 31) / 32;

    // per chunk: 4 parts x 128 rows x 4 granules(16B=8 bf16) = 2048 granules
    auto load_chunk = [&](int stage, int k0) {
        uint32_t base = tiles + stage * STAGEB;
        const int r  = tid >> 2;        // 0..63
        const int gc = tid & 3;         // granule in row
        const int k  = k0 + (gc << 3);
        #pragma unroll
        for (int i = 0; i < 8; i++) {
            const int part = i >> 1;                 // 0 Ahi,1 Alo,2 Bhi,3 Blo
            const int row  = ((i & 1) << 6) + r;     // 0..127
            uint32_t dst = base + part * TILEB + row * ROWB + (gc << 4);
            const __nv_bfloat16* mat =
                (part == 0) ? Ahi : (part == 1) ? Alo : (part == 2) ? Bhi : Blo;
            const int gr = (part < 2) ? rowBase + row : colBase + row;
            if (k < K) cpa16(dst, mat + (size_t)gr * K + k);
            else       sts_zero16(dst);
        }
    };

    load_chunk(0, 0);
    CP_COMMIT();

    for (int c = 0; c < NC; c++) {
        if (c + 1 < NC) { load_chunk((c + 1) & 1, (c + 1) * 32); CP_COMMIT(); CP_WAIT1(); }
        else            { CP_WAIT0(); }
        __syncthreads();

        uint32_t abase = tiles + (c & 1) * STAGEB;          // Ahi
        uint32_t bbase = abase + 2 * TILEB;                  // Bhi
        const int lm = lid >> 3;
        const int lr = lid & 7;

        #pragma unroll
        for (int ks = 0; ks < 2; ks++) {
            uint32_t ah[4][4], al[4][4], bh[4][2], bl[4][2];
            // A fragments: 4 m16k16 tiles, hi + lo
            #pragma unroll
            for (int mt = 0; mt < 4; mt++) {
                uint32_t r = wm * 64 + mt * 16 + ((lm & 1) << 3) + lr;
                uint32_t addr = abase + r * ROWB + (ks << 5) + ((lm >> 1) << 4);
                ldsm4(addr,         ah[mt][0], ah[mt][1], ah[mt][2], ah[mt][3]);
                ldsm4(addr + TILEB, al[mt][0], al[mt][1], al[mt][2], al[mt][3]);
            }
            // B fragments: 2 x4 loads cover 4 n8k16 tiles, hi + lo
            #pragma unroll
            for (int bt = 0; bt < 2; bt++) {
                uint32_t r = wn * 32 + bt * 16 + ((lm >> 1) << 3) + lr;
                uint32_t addr = bbase + r * ROWB + (ks << 5) + ((lm & 1) << 4);
                uint32_t t0, t1, t2, t3;
                ldsm4(addr, t0, t1, t2, t3);
                bh[2*bt][0] = t0; bh[2*bt][1] = t1; bh[2*bt+1][0] = t2; bh[2*bt+1][1] = t3;
                ldsm4(addr + TILEB, t0, t1, t2, t3);
                bl[2*bt][0] = t0; bl[2*bt][1] = t1; bl[2*bt+1][0] = t2; bl[2*bt+1][1] = t3;
            }
            #pragma unroll
            for (int mt = 0; mt < 4; mt++)
                #pragma unroll
                for (int nt = 0; nt < 4; nt++) {
                    mma_bf16(acc[mt][nt], ah[mt], bl[nt]);
                    mma_bf16(acc[mt][nt], al[mt], bh[nt]);
                    mma_bf16(acc[mt][nt], ah[mt], bh[nt]);
                }
        }
        __syncthreads();
    }

    // epilogue: c0:(g,2tg) c1:(g,2tg+1) c2:(g+8,2tg) c3:(g+8,2tg+1)
    const int g  = lid >> 2;
    const int tg = lid & 3;
    #pragma unroll
    for (int mt = 0; mt < 4; mt++) {
        int r0 = rowBase + wm * 64 + mt * 16 + g;
        #pragma unroll
        for (int nt = 0; nt < 4; nt++) {
            int cc = wn * 32 + nt * 8 + 2 * tg;
            float b0 = bsm[cc], b1 = bsm[cc + 1];
            float2 v0 = make_float2(acc[mt][nt][0] + b0, acc[mt][nt][1] + b1);
            float2 v1 = make_float2(acc[mt][nt][2] + b0, acc[mt][nt][3] + b1);
            if (relu) {
                v0.x = fmaxf(v0.x, 0.f); v0.y = fmaxf(v0.y, 0.f);
                v1.x = fmaxf(v1.x, 0.f); v1.y = fmaxf(v1.y, 0.f);
            }
            *(float2*)&C[(size_t)r0 * N + cc + colBase] = v0;
            *(float2*)&C[(size_t)(r0 + 8) * N + cc + colBase] = v1;
            if (Chi) {
                __nv_bfloat162 hh, ll;
                hh.x = __float2bfloat16_rn(v0.x);
                hh.y = __float2bfloat16_rn(v0.y);
                ll.x = __float2bfloat16_rn(v0.x - __bfloat162float(hh.x));
                ll.y = __float2bfloat16_rn(v0.y - __bfloat162float(hh.y));
                *(__nv_bfloat162*)&Chi[(size_t)r0 * N + cc + colBase] = hh;
                *(__nv_bfloat162*)&Clo[(size_t)r0 * N + cc + colBase] = ll;
                hh.x = __float2bfloat16_rn(v1.x);
                hh.y = __float2bfloat16_rn(v1.y);
                ll.x = __float2bfloat16_rn(v1.x - __bfloat162float(hh.x));
                ll.y = __float2bfloat16_rn(v1.y - __bfloat162float(hh.y));
                *(__nv_bfloat162*)&Chi[(size_t)(r0 + 8) * N + cc + colBase] = hh;
                *(__nv_bfloat162*)&Clo[(size_t)(r0 + 8) * N + cc + colBase] = ll;
            }
        }
    }
}

// ---------------- init: zero barrier counters + h double buffers -----------
__global__ void init_rec_kernel()
{
    int t = blockIdx.x * blockDim.x + threadIdx.x;
    if (t < 2) g_barctr[t] = 0u;
    if (t < 2 * 2 * 4096) g_hbuf[t] = 0.f;
}

// ---------------- persistent bidirectional LSTM recurrence -----------------
// EXACT round-4 version (proven passing at 13.9ms total).
__global__ __launch_bounds__(256) void lstm_rec_kernel(
    const float* __restrict__ xg_f, const float* __restrict__ xg_b,
    const float* __restrict__ whh_f, const float* __restrict__ whh_b,
    float* __restrict__ out)
{
    const int dir   = blockIdx.x / NBLK;
    const int blk   = blockIdx.x % NBLK;
    const int jbase = blk * 4;
    const int tid   = threadIdx.x;
    const int b     = tid >> 4;
    const int col   = tid & 15;
    const int gate  = col >> 2;
    const int jl    = col & 3;
    const int xgcol = gate * 256 + jbase + jl;

    const float* xg  = dir ? xg_b  : xg_f;
    const float* whh = dir ? whh_b : whh_f;

    __shared__ float wsm[16][260];
    __shared__ float hsm[16][260];
    __shared__ float gsm[16][16];

    for (int i = tid; i < 16 * 256; i += 256) {
        int c = i >> 8, k = i & 255;
        int g2 = c >> 2, j2 = c & 3;
        wsm[c][k] = whh[(g2 * 256 + jbase + j2) * 256 + k];
    }

    float cst = 0.f;
    const int ub = tid >> 2, uj = tid & 3;
    float* hbuf = g_hbuf + dir * 2 * 4096;
    unsigned* ctr = &g_barctr[dir];
    __syncthreads();

    for (int iter = 0; iter < T_SEQ; iter++) {
        const int par = iter & 1;
        {
            const float4* src = (const float4*)(hbuf + par * 4096);
            #pragma unroll
            for (int i = 0; i < 4; i++) {
                int id = tid * 4 + i;
                float4 v = __ldcg(&src[id]);
                int bb = id >> 6;
                int kk = (id & 63) << 2;
                *(float4*)&hsm[bb][kk] = v;
            }
        }
        __syncthreads();

        const int t = dir ? (T_SEQ - 1 - iter) : iter;
        float xv = __ldg(&xg[(size_t)(b * T_SEQ + t) * 1024 + xgcol]);

        float acc = 0.f;
        const float4* wr = (const float4*)&wsm[col][0];
        const float4* hr = (const float4*)&hsm[b][0];
        #pragma unroll 8
        for (int k4 = 0; k4 < 64; k4++) {
            float4 w = wr[k4];
            float4 h = hr[k4];
            acc = fmaf(w.x, h.x, acc);
            acc = fmaf(w.y, h.y, acc);
            acc = fmaf(w.z, h.z, acc);
            acc = fmaf(w.w, h.w, acc);
        }
        gsm[b][col] = acc + xv;
        __syncthreads();

        if (tid < 64) {
            float gi = gsm[ub][0  + uj];
            float gf = gsm[ub][4  + uj];
            float gg = gsm[ub][8  + uj];
            float go = gsm[ub][12 + uj];
            float si = 1.f / (1.f + expf(-gi));
            float sf = 1.f / (1.f + expf(-gf));
            float tg = tanhf(gg);
            float so = 1.f / (1.f + expf(-go));
            cst = sf * cst + si * tg;
            float hv = so * tanhf(cst);
            hbuf[(par ^ 1) * 4096 + ub * 256 + jbase + uj] = hv;
            out[(size_t)(ub * T_SEQ + t) * 512 + dir * 256 + jbase + uj] = hv;
            __threadfence();
        }
        __syncthreads();

        if (tid == 0) {
            atomicAdd(ctr, 1u);
            unsigned target = (unsigned)(iter + 1) * NBLK;
            while (*((volatile unsigned*)ctr) < target) { __nanosleep(32); }
        }
        __syncthreads();
        __threadfence();
    }
}

// ---------------- final FC: [16000,512] @ [29,512]^T + b -------------------
__global__ __launch_bounds__(256) void fc_kernel(
    const float* __restrict__ A, const float* __restrict__ W,
    const float* __restrict__ bias, float* __restrict__ out)
{
    __shared__ float as[8][512];
    int r0 = blockIdx.x * 8;
    for (int i = threadIdx.x; i < 8 * 512; i += 256)
        as[i >> 9][i & 511] = A[(size_t)(r0 + (i >> 9)) * 512 + (i & 511)];
    __syncthreads();

    int r = threadIdx.x >> 5;
    int c = threadIdx.x & 31;
    if (c < 29) {
        const float* w = W + c * 512;
        float acc = 0.f;
        #pragma unroll 8
        for (int k = 0; k < 512; k++) acc = fmaf(as[r][k], __ldg(&w[k]), acc);
        out[(size_t)(r0 + r) * 29 + c] = acc + bias[c];
    }
}

// ---------------- launch ---------------------------------------------------
extern "C" void kernel_launch(void* const* d_in, const int* in_sizes, int n_in,
                              void* d_out, int out_size)
{
    (void)in_sizes; (void)n_in; (void)out_size;
    const float* x        = (const float*)d_in[0];
    const float* fe_w1    = (const float*)d_in[1];
    const float* fe_b1    = (const float*)d_in[2];
    const float* fe_w2    = (const float*)d_in[3];
    const float* fe_b2    = (const float*)d_in[4];
    const float* w_ih_l0f = (const float*)d_in[5];
    const float* w_hh_l0f = (const float*)d_in[6];
    const float* b_ih_l0f = (const float*)d_in[7];
    const float* b_hh_l0f = (const float*)d_in[8];
    const float* w_ih_l0b = (const float*)d_in[9];
    const float* w_hh_l0b = (const float*)d_in[10];
    const float* b_ih_l0b = (const float*)d_in[11];
    const float* b_hh_l0b = (const float*)d_in[12];
    const float* w_ih_l1f = (const float*)d_in[13];
    const float* w_hh_l1f = (const float*)d_in[14];
    const float* b_ih_l1f = (const float*)d_in[15];
    const float* b_hh_l1f = (const float*)d_in[16];
    const float* w_ih_l1b = (const float*)d_in[17];
    const float* w_hh_l1b = (const float*)d_in[18];
    const float* b_ih_l1b = (const float*)d_in[19];
    const float* b_hh_l1b = (const float*)d_in[20];
    const float* fc_w     = (const float*)d_in[21];
    const float* fc_b     = (const float*)d_in[22];
    float* out = (float*)d_out;

    float *h1, *h2, *xgf, *xgb, *o0, *o1;
    cudaGetSymbolAddress((void**)&h1,  g_h1);
    cudaGetSymbolAddress((void**)&h2,  g_h2);
    cudaGetSymbolAddress((void**)&xgf, g_xgf);
    cudaGetSymbolAddress((void**)&xgb, g_xgb);
    cudaGetSymbolAddress((void**)&o0,  g_out0);
    cudaGetSymbolAddress((void**)&o1,  g_out1);

    __nv_bfloat16 *xhi, *xlo, *w1hi, *w1lo, *w2hi, *w2lo;
    __nv_bfloat16 *h1hi, *h1lo, *h2hi, *h2lo;
    __nv_bfloat16 *wl0fhi, *wl0flo, *wl0bhi, *wl0blo;
    __nv_bfloat16 *wl1fhi, *wl1flo, *wl1bhi, *wl1blo, *o0hi, *o0lo;
    cudaGetSymbolAddress((void**)&xhi,    g_xhi);    cudaGetSymbolAddress((void**)&xlo,    g_xlo);
    cudaGetSymbolAddress((void**)&w1hi,   g_w1hi);   cudaGetSymbolAddress((void**)&w1lo,   g_w1lo);
    cudaGetSymbolAddress((void**)&w2hi,   g_w2hi);   cudaGetSymbolAddress((void**)&w2lo,   g_w2lo);
    cudaGetSymbolAddress((void**)&h1hi,   g_h1hi);   cudaGetSymbolAddress((void**)&h1lo,   g_h1lo);
    cudaGetSymbolAddress((void**)&h2hi,   g_h2hi);   cudaGetSymbolAddress((void**)&h2lo,   g_h2lo);
    cudaGetSymbolAddress((void**)&wl0fhi, g_wl0fhi); cudaGetSymbolAddress((void**)&wl0flo, g_wl0flo);
    cudaGetSymbolAddress((void**)&wl0bhi, g_wl0bhi); cudaGetSymbolAddress((void**)&wl0blo, g_wl0blo);
    cudaGetSymbolAddress((void**)&wl1fhi, g_wl1fhi); cudaGetSymbolAddress((void**)&wl1flo, g_wl1flo);
    cudaGetSymbolAddress((void**)&wl1bhi, g_wl1bhi); cudaGetSymbolAddress((void**)&wl1blo, g_wl1blo);
    cudaGetSymbolAddress((void**)&o0hi,   g_o0hi);   cudaGetSymbolAddress((void**)&o0lo,   g_o0lo);

    cudaFuncSetAttribute(tc_gemm, cudaFuncAttributeMaxDynamicSharedMemorySize, GEMM_SMEM_BYTES);

    #define CONV(src, hi, lo, n) conv_split_kernel<<<((n) + 255) / 256, 256>>>(src, hi, lo, n)
    // input + weight splits
    CONV(x, xhi, xlo, M_ROWS * 80);
    CONV(fe_w1, w1hi, w1lo, 1024 * 80);
    CONV(fe_w2, w2hi, w2lo, 2560 * 1024);
    CONV(w_ih_l0f, wl0fhi, wl0flo, 1024 * 2560);
    CONV(w_ih_l0b, wl0bhi, wl0blo, 1024 * 2560);
    CONV(w_ih_l1f, wl1fhi, wl1flo, 1024 * 512);
    CONV(w_ih_l1b, wl1bhi, wl1blo, 1024 * 512);

    // feature extractor
    tc_gemm<<<dim3(8,  M_ROWS / 128), 256, GEMM_SMEM_BYTES>>>(
        xhi, xlo, w1hi, w1lo, fe_b1, nullptr, h1, h1hi, h1lo, M_ROWS, 1024, 80, 1);
    tc_gemm<<<dim3(20, M_ROWS / 128), 256, GEMM_SMEM_BYTES>>>(
        h1hi, h1lo, w2hi, w2lo, fe_b2, nullptr, h2, h2hi, h2lo, M_ROWS, 2560, 1024, 1);

    // layer 0: gate precompute + recurrence
    tc_gemm<<<dim3(8, M_ROWS / 128), 256, GEMM_SMEM_BYTES>>>(
        h2hi, h2lo, wl0fhi, wl0flo, b_ih_l0f, b_hh_l0f, xgf, nullptr, nullptr, M_ROWS, 1024, 2560, 0);
    tc_gemm<<<dim3(8, M_ROWS / 128), 256, GEMM_SMEM_BYTES>>>(
        h2hi, h2lo, wl0bhi, wl0blo, b_ih_l0b, b_hh_l0b, xgb, nullptr, nullptr, M_ROWS, 1024, 2560, 0);
    init_rec_kernel<<<64, 256>>>();
    lstm_rec_kernel<<<2 * NBLK, 256>>>(xgf, xgb, w_hh_l0f, w_hh_l0b, o0);

    // layer 1
    CONV(o0, o0hi, o0lo, M_ROWS * 512);
    tc_gemm<<<dim3(8, M_ROWS / 128), 256, GEMM_SMEM_BYTES>>>(
        o0hi, o0lo, wl1fhi, wl1flo, b_ih_l1f, b_hh_l1f, xgf, nullptr, nullptr, M_ROWS, 1024, 512, 0);
    tc_gemm<<<dim3(8, M_ROWS / 128), 256, GEMM_SMEM_BYTES>>>(
        o0hi, o0lo, wl1bhi, wl1blo, b_ih_l1b, b_hh_l1b, xgb, nullptr, nullptr, M_ROWS, 1024, 512, 0);
    init_rec_kernel<<<64, 256>>>();
    lstm_rec_kernel<<<2 * NBLK, 256>>>(xgf, xgb, w_hh_l1f, w_hh_l1b, o1);

    // classifier
    fc_kernel<<<M_ROWS / 8, 256>>>(o1, fc_w, fc_b, out);
    #undef CONV
}